// round 1
// baseline (speedup 1.0000x reference)
#include <cuda_runtime.h>
#include <cuda_bf16.h>

#define D_MODEL 1024
#define NHEAD   16
#define HDIM    64
#define BATCH   4
#define SEQ     2048
#define MROWS   (BATCH * SEQ)      /* 8192 */
#define QKV_N   (3 * D_MODEL)      /* 3072 */

// Scratch (no allocs allowed): qkv activations + attention output
__device__ float g_qkv[(size_t)MROWS * QKV_N];   // ~100.7 MB
__device__ float g_y[(size_t)MROWS * D_MODEL];   // ~33.6 MB

// ---------------------------------------------------------------------------
// NT GEMM: C[M,N] = A[M,K] * B[N,K]^T, fp32.
// BM=BN=128, BK=8, 256 threads, 8x8 per-thread microtile.
// Smem tiles stored k-major so the inner loop does conflict-free LDS.128.
// ---------------------------------------------------------------------------
__global__ void __launch_bounds__(256) gemm_nt_kernel(
    const float* __restrict__ A, const float* __restrict__ B,
    float* __restrict__ C, int M, int N, int K)
{
    __shared__ float As[8][128];
    __shared__ float Bs[8][128];

    const int m0 = blockIdx.y * 128;
    const int n0 = blockIdx.x * 128;
    const int tid = threadIdx.x;
    const int ty = tid >> 4;      // 0..15 (m dir)
    const int tx = tid & 15;      // 0..15 (n dir)

    const int lrow = tid >> 1;          // 0..127
    const int lk   = (tid & 1) * 4;     // 0 or 4

    const float* Ag = A + (size_t)(m0 + lrow) * K + lk;
    const float* Bg = B + (size_t)(n0 + lrow) * K + lk;

    float acc[8][8];
#pragma unroll
    for (int i = 0; i < 8; i++)
#pragma unroll
        for (int j = 0; j < 8; j++) acc[i][j] = 0.f;

    for (int k0 = 0; k0 < K; k0 += 8) {
        float4 av = *(const float4*)(Ag + k0);
        float4 bv = *(const float4*)(Bg + k0);
        As[lk + 0][lrow] = av.x; As[lk + 1][lrow] = av.y;
        As[lk + 2][lrow] = av.z; As[lk + 3][lrow] = av.w;
        Bs[lk + 0][lrow] = bv.x; Bs[lk + 1][lrow] = bv.y;
        Bs[lk + 2][lrow] = bv.z; Bs[lk + 3][lrow] = bv.w;
        __syncthreads();

#pragma unroll
        for (int kk = 0; kk < 8; kk++) {
            float4 a0 = *(const float4*)&As[kk][ty * 8];
            float4 a1 = *(const float4*)&As[kk][ty * 8 + 4];
            float4 b0 = *(const float4*)&Bs[kk][tx * 8];
            float4 b1 = *(const float4*)&Bs[kk][tx * 8 + 4];
            float a[8] = {a0.x, a0.y, a0.z, a0.w, a1.x, a1.y, a1.z, a1.w};
            float b[8] = {b0.x, b0.y, b0.z, b0.w, b1.x, b1.y, b1.z, b1.w};
#pragma unroll
            for (int i = 0; i < 8; i++)
#pragma unroll
                for (int j = 0; j < 8; j++)
                    acc[i][j] = fmaf(a[i], b[j], acc[i][j]);
        }
        __syncthreads();
    }

#pragma unroll
    for (int i = 0; i < 8; i++) {
        float* Cp = C + (size_t)(m0 + ty * 8 + i) * N + n0 + tx * 8;
        *(float4*)(Cp + 0) = make_float4(acc[i][0], acc[i][1], acc[i][2], acc[i][3]);
        *(float4*)(Cp + 4) = make_float4(acc[i][4], acc[i][5], acc[i][6], acc[i][7]);
    }
}

// ---------------------------------------------------------------------------
// Flash-style causal attention, fp32.
// Grid: (T/64, B*H). Block: 256 threads.
// Per CTA: 64 queries x Dh=64. Iterate 64-key tiles up to the causal bound.
// Thread (r = tid/16, c = tid%16): owns q rows r*4..r*4+3, n/dim cols c*4..c*4+3.
// Q,K in smem d-major (conflict-free reads); P staged via smem for P@V.
// Dynamic smem: 4 * 64*64*4B = 64 KB.
// ---------------------------------------------------------------------------
__global__ void __launch_bounds__(256) attn_kernel(
    const float* __restrict__ qkv, float* __restrict__ y)
{
    extern __shared__ float sm[];
    float (*sQ)[64] = (float(*)[64])(sm);           // [d][q]
    float (*sK)[64] = (float(*)[64])(sm + 4096);    // [d][k]
    float (*sV)[64] = (float(*)[64])(sm + 8192);    // [k][d]
    float (*sP)[64] = (float(*)[64])(sm + 12288);   // [q][k]

    const int qt = blockIdx.x;        // q tile 0..31
    const int bh = blockIdx.y;        // 0..63
    const int b  = bh >> 4;
    const int h  = bh & 15;
    const int q0 = qt * 64;
    const int tid = threadIdx.x;
    const int r = tid >> 4;           // 0..15
    const int c = tid & 15;           // 0..15
    const float scale = 0.125f;       // 1/sqrt(64)

    const size_t base = (size_t)b * SEQ * QKV_N;
    const int lrow = tid >> 2;            // 0..63
    const int lseg = (tid & 3) * 16;      // 0,16,32,48

    // Load Q tile (pre-scaled), d-major
    {
        const float* src = qkv + base + (size_t)(q0 + lrow) * QKV_N + h * HDIM + lseg;
#pragma unroll
        for (int p = 0; p < 16; p += 4) {
            float4 v = *(const float4*)(src + p);
            int d = lseg + p;
            sQ[d + 0][lrow] = v.x * scale;
            sQ[d + 1][lrow] = v.y * scale;
            sQ[d + 2][lrow] = v.z * scale;
            sQ[d + 3][lrow] = v.w * scale;
        }
    }

    float o[4][4];
    float m_i[4], l_i[4];
#pragma unroll
    for (int i = 0; i < 4; i++) {
        m_i[i] = -1e30f; l_i[i] = 0.f;
#pragma unroll
        for (int j = 0; j < 4; j++) o[i][j] = 0.f;
    }

    const int ntile = qt + 1;  // causal bound
    for (int t = 0; t < ntile; t++) {
        const int k0 = t * 64;
        __syncthreads();   // protect sK/sV/sP from previous iteration readers
        {
            const float* ksrc = qkv + base + (size_t)(k0 + lrow) * QKV_N + D_MODEL     + h * HDIM + lseg;
            const float* vsrc = qkv + base + (size_t)(k0 + lrow) * QKV_N + 2 * D_MODEL + h * HDIM + lseg;
#pragma unroll
            for (int p = 0; p < 16; p += 4) {
                float4 kv = *(const float4*)(ksrc + p);
                int d = lseg + p;
                sK[d + 0][lrow] = kv.x; sK[d + 1][lrow] = kv.y;
                sK[d + 2][lrow] = kv.z; sK[d + 3][lrow] = kv.w;
                float4 vv = *(const float4*)(vsrc + p);
                *(float4*)&sV[lrow][d] = vv;
            }
        }
        __syncthreads();

        // S = Q * K^T (4x4 per thread)
        float s[4][4];
#pragma unroll
        for (int i = 0; i < 4; i++)
#pragma unroll
            for (int j = 0; j < 4; j++) s[i][j] = 0.f;

#pragma unroll 8
        for (int d = 0; d < 64; d++) {
            float4 qa = *(const float4*)&sQ[d][r * 4];
            float4 kb = *(const float4*)&sK[d][c * 4];
            float qv[4] = {qa.x, qa.y, qa.z, qa.w};
            float kw[4] = {kb.x, kb.y, kb.z, kb.w};
#pragma unroll
            for (int i = 0; i < 4; i++)
#pragma unroll
                for (int j = 0; j < 4; j++)
                    s[i][j] = fmaf(qv[i], kw[j], s[i][j]);
        }

        if (k0 == q0) {   // only the diagonal tile needs masking
#pragma unroll
            for (int i = 0; i < 4; i++)
#pragma unroll
                for (int j = 0; j < 4; j++)
                    if (c * 4 + j > r * 4 + i) s[i][j] = -1e30f;
        }

        // Online softmax per row (16-lane groups, warp-aligned)
#pragma unroll
        for (int i = 0; i < 4; i++) {
            float mx = fmaxf(fmaxf(s[i][0], s[i][1]), fmaxf(s[i][2], s[i][3]));
#pragma unroll
            for (int off = 8; off; off >>= 1)
                mx = fmaxf(mx, __shfl_xor_sync(0xffffffffu, mx, off));
            float mnew = fmaxf(m_i[i], mx);
            float alpha = __expf(m_i[i] - mnew);
            float psum = 0.f;
#pragma unroll
            for (int j = 0; j < 4; j++) {
                float p = __expf(s[i][j] - mnew);
                s[i][j] = p;
                psum += p;
            }
#pragma unroll
            for (int off = 8; off; off >>= 1)
                psum += __shfl_xor_sync(0xffffffffu, psum, off);
            l_i[i] = l_i[i] * alpha + psum;
            m_i[i] = mnew;
#pragma unroll
            for (int j = 0; j < 4; j++) o[i][j] *= alpha;
            *(float4*)&sP[r * 4 + i][c * 4] = make_float4(s[i][0], s[i][1], s[i][2], s[i][3]);
        }
        __syncthreads();

        // O += P @ V
#pragma unroll 8
        for (int k = 0; k < 64; k++) {
            float4 vv = *(const float4*)&sV[k][c * 4];
            float vb[4] = {vv.x, vv.y, vv.z, vv.w};
            float pv[4];
#pragma unroll
            for (int i = 0; i < 4; i++) pv[i] = sP[r * 4 + i][k];
#pragma unroll
            for (int i = 0; i < 4; i++)
#pragma unroll
                for (int j = 0; j < 4; j++)
                    o[i][j] = fmaf(pv[i], vb[j], o[i][j]);
        }
    }

    // Write y in [B,T,H,Dh] == [M, 1024] row-major for the proj GEMM
#pragma unroll
    for (int i = 0; i < 4; i++) {
        int q = q0 + r * 4 + i;
        float inv = 1.f / l_i[i];
        float* dst = y + (size_t)(b * SEQ + q) * D_MODEL + h * HDIM + c * 4;
        *(float4*)dst = make_float4(o[i][0] * inv, o[i][1] * inv, o[i][2] * inv, o[i][3] * inv);
    }
}

// ---------------------------------------------------------------------------
extern "C" void kernel_launch(void* const* d_in, const int* in_sizes, int n_in,
                              void* d_out, int out_size)
{
    const float* x      = (const float*)d_in[0];
    const float* w_qkv  = (const float*)d_in[1];
    const float* w_proj = (const float*)d_in[2];
    float* out = (float*)d_out;

    float* qkv = nullptr;
    float* yb  = nullptr;
    cudaGetSymbolAddress((void**)&qkv, g_qkv);
    cudaGetSymbolAddress((void**)&yb, g_y);

    cudaFuncSetAttribute(attn_kernel, cudaFuncAttributeMaxDynamicSharedMemorySize, 65536);

    // 1) QKV = X * Wqkv^T   [8192 x 3072]
    {
        dim3 grid(QKV_N / 128, MROWS / 128);
        gemm_nt_kernel<<<grid, 256>>>(x, w_qkv, qkv, MROWS, QKV_N, D_MODEL);
    }
    // 2) Causal attention -> y [8192 x 1024]
    {
        dim3 grid(SEQ / 64, BATCH * NHEAD);
        attn_kernel<<<grid, 256, 65536>>>(qkv, yb);
    }
    // 3) out = y * Wproj^T  [8192 x 1024]
    {
        dim3 grid(D_MODEL / 128, MROWS / 128);
        gemm_nt_kernel<<<grid, 256>>>(yb, w_proj, out, MROWS, D_MODEL, D_MODEL);
    }
}

// round 3
// speedup vs baseline: 2.0354x; 2.0354x over previous
#include <cuda_runtime.h>
#include <cuda_bf16.h>
#include <cstdint>

#define D_MODEL 1024
#define NHEAD   16
#define HDIM    64
#define BATCH   4
#define SEQ     2048
#define MROWS   (BATCH * SEQ)      /* 8192 */
#define QKV_N   (3 * D_MODEL)      /* 3072 */

// Arch-specific feature gate: tcgen05/TMEM only exist on sm_10xa / sm_10xf
#if defined(__CUDA_ARCH_FEAT_SM103_ALL) || defined(__CUDA_ARCH_FEAT_SM100_ALL) || \
    defined(__CUDA_ARCH_FEAT_SM101_ALL) || \
    (defined(__CUDA_ARCH_SPECIFIC__) && (__CUDA_ARCH_SPECIFIC__ >= 1000)) || \
    (defined(__CUDA_ARCH_FAMILY_SPECIFIC__) && (__CUDA_ARCH_FAMILY_SPECIFIC__ >= 1000))
#define TC5 1
#else
#define TC5 0
#endif

// ---------------- scratch (no allocs allowed) ----------------
__device__ float g_qkv[(size_t)MROWS * QKV_N];   // fp32 qkv activations
__device__ float g_y[(size_t)MROWS * D_MODEL];   // fp32 attention output

__device__ __nv_bfloat16 g_xh[(size_t)MROWS * D_MODEL];
__device__ __nv_bfloat16 g_xl[(size_t)MROWS * D_MODEL];
__device__ __nv_bfloat16 g_wqh[(size_t)QKV_N * D_MODEL];
__device__ __nv_bfloat16 g_wql[(size_t)QKV_N * D_MODEL];
__device__ __nv_bfloat16 g_yh[(size_t)MROWS * D_MODEL];
__device__ __nv_bfloat16 g_yl[(size_t)MROWS * D_MODEL];
__device__ __nv_bfloat16 g_wph[(size_t)D_MODEL * D_MODEL];
__device__ __nv_bfloat16 g_wpl[(size_t)D_MODEL * D_MODEL];

// ---------------- generic helpers (legal on all targets) ----------------
__device__ __forceinline__ uint32_t smem_u32(const void* p) {
    uint32_t a;
    asm("{ .reg .u64 t; cvta.to.shared.u64 t, %1; cvt.u32.u64 %0, t; }" : "=r"(a) : "l"(p));
    return a;
}
__device__ __forceinline__ void cp16(uint32_t dst, const void* src) {
    asm volatile("cp.async.cg.shared.global [%0], [%1], 16;" :: "r"(dst), "l"(src) : "memory");
}
__device__ __forceinline__ void cp_commit() { asm volatile("cp.async.commit_group;" ::: "memory"); }
__device__ __forceinline__ void cp_wait1()  { asm volatile("cp.async.wait_group 1;" ::: "memory"); }
__device__ __forceinline__ void cp_wait0()  { asm volatile("cp.async.wait_group 0;" ::: "memory"); }
__device__ __forceinline__ uint32_t swz(uint32_t x) { return x ^ ((x >> 3) & 0x70); }

// ---------------- tcgen05 helpers (sm_103a pass only) ----------------
#if TC5
__device__ __forceinline__ uint32_t elect_one() {
    uint32_t p;
    asm volatile("{\n\t.reg .pred p;\n\telect.sync _|p, 0xFFFFFFFF;\n\tselp.b32 %0, 1, 0, p;\n\t}" : "=r"(p));
    return p;
}
__device__ __forceinline__ void mbar_init(uint32_t mbar, uint32_t cnt) {
    asm volatile("mbarrier.init.shared.b64 [%0], %1;" :: "r"(mbar), "r"(cnt) : "memory");
}
__device__ __forceinline__ void mbar_wait(uint32_t mbar, uint32_t parity) {
    asm volatile(
        "{\n\t.reg .pred P;\n\t"
        "W%=:\n\t"
        "mbarrier.try_wait.parity.shared.b64 P, [%0], %1;\n\t"
        "@!P bra W%=;\n\t}"
        :: "r"(mbar), "r"(parity) : "memory");
}
__device__ __forceinline__ void tmem_alloc(uint32_t smem_dst, uint32_t ncols) {
    asm volatile("tcgen05.alloc.cta_group::1.sync.aligned.shared::cta.b32 [%0], %1;"
                 :: "r"(smem_dst), "r"(ncols) : "memory");
}
__device__ __forceinline__ void tmem_dealloc(uint32_t tmem, uint32_t ncols) {
    asm volatile("tcgen05.dealloc.cta_group::1.sync.aligned.b32 %0, %1;" :: "r"(tmem), "r"(ncols));
}
__device__ __forceinline__ void tmem_relinquish() {
    asm volatile("tcgen05.relinquish_alloc_permit.cta_group::1.sync.aligned;");
}
__device__ __forceinline__ void tc_commit(uint32_t mbar) {
    asm volatile("tcgen05.commit.cta_group::1.mbarrier::arrive::one.shared::cluster.b64 [%0];"
                 :: "r"(mbar) : "memory");
}
__device__ __forceinline__ void tc_fence_after() {
    asm volatile("tcgen05.fence::after_thread_sync;" ::: "memory");
}
__device__ __forceinline__ void fence_async_proxy() {
    asm volatile("fence.proxy.async.shared::cta;" ::: "memory");
}
__device__ __forceinline__ void mma_bf16_ss(uint32_t d, uint64_t a, uint64_t b,
                                            uint32_t idesc, uint32_t acc) {
    asm volatile(
        "{\n\t.reg .pred p;\n\t"
        "setp.ne.u32 p, %5, 0;\n\t"
        "tcgen05.mma.cta_group::1.kind::f16 [%0], %1, %2, %3, {%4, %4, %4, %4}, p;\n\t}"
        :: "r"(d), "l"(a), "l"(b), "r"(idesc), "r"(0u), "r"(acc) : "memory");
}
__device__ __forceinline__ uint64_t mkdesc(uint32_t addr) {
    // SW128, Blackwell version=1, SBO=64, LBO=1 (K-major, 128B rows)
    constexpr uint64_t base = (uint64_t(2) << 61) | (uint64_t(1) << 46)
                            | (uint64_t(64) << 32) | (uint64_t(1) << 16);
    return base | ((addr >> 4) & 0x3FFF);
}
#define LDTM_X32(r, tmem_addr) \
    asm volatile( \
        "tcgen05.ld.sync.aligned.32x32b.x32.b32 " \
        "{%0, %1, %2, %3, %4, %5, %6, %7, " \
        " %8, %9, %10, %11, %12, %13, %14, %15, " \
        " %16, %17, %18, %19, %20, %21, %22, %23, " \
        " %24, %25, %26, %27, %28, %29, %30, %31}, [%32];" \
        : "=r"((r)[0]),  "=r"((r)[1]),  "=r"((r)[2]),  "=r"((r)[3]), \
          "=r"((r)[4]),  "=r"((r)[5]),  "=r"((r)[6]),  "=r"((r)[7]), \
          "=r"((r)[8]),  "=r"((r)[9]),  "=r"((r)[10]), "=r"((r)[11]), \
          "=r"((r)[12]), "=r"((r)[13]), "=r"((r)[14]), "=r"((r)[15]), \
          "=r"((r)[16]), "=r"((r)[17]), "=r"((r)[18]), "=r"((r)[19]), \
          "=r"((r)[20]), "=r"((r)[21]), "=r"((r)[22]), "=r"((r)[23]), \
          "=r"((r)[24]), "=r"((r)[25]), "=r"((r)[26]), "=r"((r)[27]), \
          "=r"((r)[28]), "=r"((r)[29]), "=r"((r)[30]), "=r"((r)[31]) \
        : "r"(tmem_addr))
#define TC_WAIT_LD() asm volatile("tcgen05.wait::ld.sync.aligned;" ::: "memory")
#endif  // TC5

// ---------------- fp32 -> bf16 hi/lo split ----------------
__global__ void __launch_bounds__(256) split_bf16_kernel(
    const float* __restrict__ in, __nv_bfloat16* __restrict__ hi,
    __nv_bfloat16* __restrict__ lo, int n4)
{
    int i = blockIdx.x * blockDim.x + threadIdx.x;
    if (i >= n4) return;
    float4 v = ((const float4*)in)[i];
    __nv_bfloat16 h0 = __float2bfloat16_rn(v.x);
    __nv_bfloat16 h1 = __float2bfloat16_rn(v.y);
    __nv_bfloat16 h2 = __float2bfloat16_rn(v.z);
    __nv_bfloat16 h3 = __float2bfloat16_rn(v.w);
    __nv_bfloat16 l0 = __float2bfloat16_rn(v.x - __bfloat162float(h0));
    __nv_bfloat16 l1 = __float2bfloat16_rn(v.y - __bfloat162float(h1));
    __nv_bfloat16 l2 = __float2bfloat16_rn(v.z - __bfloat162float(h2));
    __nv_bfloat16 l3 = __float2bfloat16_rn(v.w - __bfloat162float(h3));
    ((__nv_bfloat162*)hi)[2 * i + 0] = __nv_bfloat162(h0, h1);
    ((__nv_bfloat162*)hi)[2 * i + 1] = __nv_bfloat162(h2, h3);
    ((__nv_bfloat162*)lo)[2 * i + 0] = __nv_bfloat162(l0, l1);
    ((__nv_bfloat162*)lo)[2 * i + 1] = __nv_bfloat162(l2, l3);
}

// ---------------- GEMM: C[M,N] = A[M,K] * B[N,K]^T ----------------
// bf16 3-term split (AhBh + AhBl + AlBh), fp32 accumulate.
// Tile: BM=128, BN=256, BK=64. 2-stage cp.async pipeline. 256 threads.
#define GBM 128
#define GBN 256
#define GBK 64
#define AH_OFF 0
#define AL_OFF 16384
#define BH_OFF 32768
#define BL_OFF 65536
#define STAGE_BYTES 98304
#define GEMM_DSM (1024 + 2 * STAGE_BYTES)
#define GEMM_IDESC 0x8400490u   /* f32 dtype, bf16 a/b, M=128, N=256 */

__device__ __forceinline__ void load_stage(
    uint32_t sbase, const __nv_bfloat16* __restrict__ Ah, const __nv_bfloat16* __restrict__ Al,
    const __nv_bfloat16* __restrict__ Bh, const __nv_bfloat16* __restrict__ Bl,
    int m0, int n0, int kc, int K, int tid)
{
    const int k0 = kc * GBK;
    for (int i = tid; i < 1024; i += 256) {     // A: 128 rows x 8 segs (hi+lo)
        int row = i >> 3, seg = i & 7;
        uint32_t so = swz((uint32_t)(row * 128 + seg * 16));
        size_t g = (size_t)(m0 + row) * K + k0 + seg * 8;
        cp16(sbase + AH_OFF + so, Ah + g);
        cp16(sbase + AL_OFF + so, Al + g);
    }
    for (int i = tid; i < 2048; i += 256) {     // B: 256 rows x 8 segs (hi+lo)
        int row = i >> 3, seg = i & 7;
        uint32_t so = swz((uint32_t)(row * 128 + seg * 16));
        size_t g = (size_t)(n0 + row) * K + k0 + seg * 8;
        cp16(sbase + BH_OFF + so, Bh + g);
        cp16(sbase + BL_OFF + so, Bl + g);
    }
    cp_commit();
}

__global__ void __launch_bounds__(256)
gemm_bf16x3_kernel(const __nv_bfloat16* __restrict__ Ah, const __nv_bfloat16* __restrict__ Al,
                   const __nv_bfloat16* __restrict__ Bh, const __nv_bfloat16* __restrict__ Bl,
                   float* __restrict__ C, int N, int K)
{
    extern __shared__ char dsm[];
    const int tid = threadIdx.x;
    const int m0 = blockIdx.y * GBM;
    const int n0 = blockIdx.x * GBN;
    uint32_t tile = (smem_u32(dsm) + 1023) & ~1023u;
    const int NC = K / GBK;

#if TC5
    // ---------------- tcgen05 path ----------------
    __shared__ uint32_t s_tmem;
    __shared__ __align__(8) unsigned long long s_mbar[2];
    const int wid = tid >> 5;
    const int lane = tid & 31;

    if (wid == 0) {
        tmem_alloc(smem_u32(&s_tmem), 256);
        tmem_relinquish();
    }
    if (tid == 0) {
        mbar_init(smem_u32(&s_mbar[0]), 1);
        mbar_init(smem_u32(&s_mbar[1]), 1);
    }
    __syncthreads();
    const uint32_t tmem = s_tmem;
    const uint32_t mb[2] = { smem_u32(&s_mbar[0]), smem_u32(&s_mbar[1]) };

    load_stage(tile + 0 * STAGE_BYTES, Ah, Al, Bh, Bl, m0, n0, 0, K, tid);
    load_stage(tile + 1 * STAGE_BYTES, Ah, Al, Bh, Bl, m0, n0, 1, K, tid);

    uint32_t ph[2] = {0, 0};
    for (int c = 0; c < NC; c++) {
        const int s = c & 1;
        if (c + 1 < NC) cp_wait1(); else cp_wait0();
        fence_async_proxy();
        __syncthreads();

        if (wid == 0 && elect_one()) {
            uint32_t sb = tile + s * STAGE_BYTES;
            uint64_t dah = mkdesc(sb + AH_OFF);
            uint64_t dal = mkdesc(sb + AL_OFF);
            uint64_t dbh = mkdesc(sb + BH_OFF);
            uint64_t dbl = mkdesc(sb + BL_OFF);
#pragma unroll
            for (int kk = 0; kk < 4; kk++) {
                mma_bf16_ss(tmem, dah + kk * 2, dbh + kk * 2, GEMM_IDESC,
                            (c == 0 && kk == 0) ? 0u : 1u);
                mma_bf16_ss(tmem, dah + kk * 2, dbl + kk * 2, GEMM_IDESC, 1u);
                mma_bf16_ss(tmem, dal + kk * 2, dbh + kk * 2, GEMM_IDESC, 1u);
            }
            tc_commit(mb[s]);
        }

        if (c + 2 < NC) {
            mbar_wait(mb[s], ph[s]);   // chunk c's MMA done -> stage reusable
            ph[s] ^= 1;
            load_stage(tile + s * STAGE_BYTES, Ah, Al, Bh, Bl, m0, n0, c + 2, K, tid);
        }
    }
    mbar_wait(mb[0], ph[0]);
    mbar_wait(mb[1], ph[1]);
    tc_fence_after();

    {   // epilogue: warps 0-3 -> cols [0,128), warps 4-7 -> cols [128,256)
        const int colbase = (wid >> 2) * 128;
        const int row = m0 + (wid & 3) * 32 + lane;
#pragma unroll
        for (int cb = 0; cb < 4; cb++) {
            uint32_t r[32];
            LDTM_X32(r, tmem + colbase + cb * 32);
            TC_WAIT_LD();
            float* Cp = C + (size_t)row * N + n0 + colbase + cb * 32;
#pragma unroll
            for (int j = 0; j < 8; j++) {
                *(float4*)(Cp + j * 4) = make_float4(
                    __uint_as_float(r[j * 4 + 0]), __uint_as_float(r[j * 4 + 1]),
                    __uint_as_float(r[j * 4 + 2]), __uint_as_float(r[j * 4 + 3]));
            }
        }
    }
    __syncthreads();
    if (wid == 0) tmem_dealloc(tmem, 256);

#else
    // ---------------- portable FFMA fallback (correctness safety net) ----------------
    const int ty = tid >> 4;        // 0..15 -> rows ty*8..+8
    const int tx = tid & 15;        // 0..15 -> cols tx*16..+16
    float acc[8][16];
#pragma unroll
    for (int i = 0; i < 8; i++)
#pragma unroll
        for (int j = 0; j < 16; j++) acc[i][j] = 0.f;

    load_stage(tile + 0 * STAGE_BYTES, Ah, Al, Bh, Bl, m0, n0, 0, K, tid);
    if (NC > 1) load_stage(tile + 1 * STAGE_BYTES, Ah, Al, Bh, Bl, m0, n0, 1, K, tid);

    for (int c = 0; c < NC; c++) {
        const int s = c & 1;
        if (c + 1 < NC) cp_wait1(); else cp_wait0();
        __syncthreads();
        const char* sb = dsm + (tile - smem_u32(dsm)) + s * STAGE_BYTES;
        for (int kk = 0; kk < GBK; kk++) {
            float a[8], b[16];
#pragma unroll
            for (int i = 0; i < 8; i++) {
                uint32_t off = swz((uint32_t)((ty * 8 + i) * 128 + kk * 2));
                a[i] = __bfloat162float(*(const __nv_bfloat16*)(sb + AH_OFF + off))
                     + __bfloat162float(*(const __nv_bfloat16*)(sb + AL_OFF + off));
            }
#pragma unroll
            for (int j = 0; j < 16; j++) {
                uint32_t off = swz((uint32_t)((tx * 16 + j) * 128 + kk * 2));
                b[j] = __bfloat162float(*(const __nv_bfloat16*)(sb + BH_OFF + off))
                     + __bfloat162float(*(const __nv_bfloat16*)(sb + BL_OFF + off));
            }
#pragma unroll
            for (int i = 0; i < 8; i++)
#pragma unroll
                for (int j = 0; j < 16; j++)
                    acc[i][j] = fmaf(a[i], b[j], acc[i][j]);
        }
        __syncthreads();
        if (c + 2 < NC)
            load_stage(tile + s * STAGE_BYTES, Ah, Al, Bh, Bl, m0, n0, c + 2, K, tid);
    }
#pragma unroll
    for (int i = 0; i < 8; i++) {
        float* Cp = C + (size_t)(m0 + ty * 8 + i) * N + n0 + tx * 16;
#pragma unroll
        for (int j = 0; j < 16; j += 4)
            *(float4*)(Cp + j) = make_float4(acc[i][j], acc[i][j+1], acc[i][j+2], acc[i][j+3]);
    }
#endif
}

// ---------------------------------------------------------------------------
// Flash-style causal attention, fp32 (unchanged, passing).
// ---------------------------------------------------------------------------
__global__ void __launch_bounds__(256) attn_kernel(
    const float* __restrict__ qkv, float* __restrict__ y)
{
    extern __shared__ float sm[];
    float (*sQ)[64] = (float(*)[64])(sm);
    float (*sK)[64] = (float(*)[64])(sm + 4096);
    float (*sV)[64] = (float(*)[64])(sm + 8192);
    float (*sP)[64] = (float(*)[64])(sm + 12288);

    const int qt = blockIdx.x;
    const int bh = blockIdx.y;
    const int b  = bh >> 4;
    const int h  = bh & 15;
    const int q0 = qt * 64;
    const int tid = threadIdx.x;
    const int r = tid >> 4;
    const int c = tid & 15;
    const float scale = 0.125f;

    const size_t base = (size_t)b * SEQ * QKV_N;
    const int lrow = tid >> 2;
    const int lseg = (tid & 3) * 16;

    {
        const float* src = qkv + base + (size_t)(q0 + lrow) * QKV_N + h * HDIM + lseg;
#pragma unroll
        for (int p = 0; p < 16; p += 4) {
            float4 v = *(const float4*)(src + p);
            int d = lseg + p;
            sQ[d + 0][lrow] = v.x * scale;
            sQ[d + 1][lrow] = v.y * scale;
            sQ[d + 2][lrow] = v.z * scale;
            sQ[d + 3][lrow] = v.w * scale;
        }
    }

    float o[4][4];
    float m_i[4], l_i[4];
#pragma unroll
    for (int i = 0; i < 4; i++) {
        m_i[i] = -1e30f; l_i[i] = 0.f;
#pragma unroll
        for (int j = 0; j < 4; j++) o[i][j] = 0.f;
    }

    const int ntile = qt + 1;
    for (int t = 0; t < ntile; t++) {
        const int k0 = t * 64;
        __syncthreads();
        {
            const float* ksrc = qkv + base + (size_t)(k0 + lrow) * QKV_N + D_MODEL     + h * HDIM + lseg;
            const float* vsrc = qkv + base + (size_t)(k0 + lrow) * QKV_N + 2 * D_MODEL + h * HDIM + lseg;
#pragma unroll
            for (int p = 0; p < 16; p += 4) {
                float4 kv = *(const float4*)(ksrc + p);
                int d = lseg + p;
                sK[d + 0][lrow] = kv.x; sK[d + 1][lrow] = kv.y;
                sK[d + 2][lrow] = kv.z; sK[d + 3][lrow] = kv.w;
                float4 vv = *(const float4*)(vsrc + p);
                *(float4*)&sV[lrow][d] = vv;
            }
        }
        __syncthreads();

        float s[4][4];
#pragma unroll
        for (int i = 0; i < 4; i++)
#pragma unroll
            for (int j = 0; j < 4; j++) s[i][j] = 0.f;

#pragma unroll 8
        for (int d = 0; d < 64; d++) {
            float4 qa = *(const float4*)&sQ[d][r * 4];
            float4 kb = *(const float4*)&sK[d][c * 4];
            float qv[4] = {qa.x, qa.y, qa.z, qa.w};
            float kw[4] = {kb.x, kb.y, kb.z, kb.w};
#pragma unroll
            for (int i = 0; i < 4; i++)
#pragma unroll
                for (int j = 0; j < 4; j++)
                    s[i][j] = fmaf(qv[i], kw[j], s[i][j]);
        }

        if (k0 == q0) {
#pragma unroll
            for (int i = 0; i < 4; i++)
#pragma unroll
                for (int j = 0; j < 4; j++)
                    if (c * 4 + j > r * 4 + i) s[i][j] = -1e30f;
        }

#pragma unroll
        for (int i = 0; i < 4; i++) {
            float mx = fmaxf(fmaxf(s[i][0], s[i][1]), fmaxf(s[i][2], s[i][3]));
#pragma unroll
            for (int off = 8; off; off >>= 1)
                mx = fmaxf(mx, __shfl_xor_sync(0xffffffffu, mx, off));
            float mnew = fmaxf(m_i[i], mx);
            float alpha = __expf(m_i[i] - mnew);
            float psum = 0.f;
#pragma unroll
            for (int j = 0; j < 4; j++) {
                float p = __expf(s[i][j] - mnew);
                s[i][j] = p;
                psum += p;
            }
#pragma unroll
            for (int off = 8; off; off >>= 1)
                psum += __shfl_xor_sync(0xffffffffu, psum, off);
            l_i[i] = l_i[i] * alpha + psum;
            m_i[i] = mnew;
#pragma unroll
            for (int j = 0; j < 4; j++) o[i][j] *= alpha;
            *(float4*)&sP[r * 4 + i][c * 4] = make_float4(s[i][0], s[i][1], s[i][2], s[i][3]);
        }
        __syncthreads();

#pragma unroll 8
        for (int k = 0; k < 64; k++) {
            float4 vv = *(const float4*)&sV[k][c * 4];
            float vb[4] = {vv.x, vv.y, vv.z, vv.w};
            float pv[4];
#pragma unroll
            for (int i = 0; i < 4; i++) pv[i] = sP[r * 4 + i][k];
#pragma unroll
            for (int i = 0; i < 4; i++)
#pragma unroll
                for (int j = 0; j < 4; j++)
                    o[i][j] = fmaf(pv[i], vb[j], o[i][j]);
        }
    }

#pragma unroll
    for (int i = 0; i < 4; i++) {
        int q = q0 + r * 4 + i;
        float inv = 1.f / l_i[i];
        float* dst = y + (size_t)(b * SEQ + q) * D_MODEL + h * HDIM + c * 4;
        *(float4*)dst = make_float4(o[i][0] * inv, o[i][1] * inv, o[i][2] * inv, o[i][3] * inv);
    }
}

// ---------------------------------------------------------------------------
extern "C" void kernel_launch(void* const* d_in, const int* in_sizes, int n_in,
                              void* d_out, int out_size)
{
    const float* x      = (const float*)d_in[0];
    const float* w_qkv  = (const float*)d_in[1];
    const float* w_proj = (const float*)d_in[2];
    float* out = (float*)d_out;

    float *qkv, *yb;
    __nv_bfloat16 *xh, *xl, *wqh, *wql, *yh, *yl, *wph, *wpl;
    cudaGetSymbolAddress((void**)&qkv, g_qkv);
    cudaGetSymbolAddress((void**)&yb,  g_y);
    cudaGetSymbolAddress((void**)&xh,  g_xh);
    cudaGetSymbolAddress((void**)&xl,  g_xl);
    cudaGetSymbolAddress((void**)&wqh, g_wqh);
    cudaGetSymbolAddress((void**)&wql, g_wql);
    cudaGetSymbolAddress((void**)&yh,  g_yh);
    cudaGetSymbolAddress((void**)&yl,  g_yl);
    cudaGetSymbolAddress((void**)&wph, g_wph);
    cudaGetSymbolAddress((void**)&wpl, g_wpl);

    cudaFuncSetAttribute(attn_kernel, cudaFuncAttributeMaxDynamicSharedMemorySize, 65536);
    cudaFuncSetAttribute(gemm_bf16x3_kernel, cudaFuncAttributeMaxDynamicSharedMemorySize, GEMM_DSM);

    // split inputs to bf16 hi/lo
    {
        int n4 = MROWS * D_MODEL / 4;
        split_bf16_kernel<<<(n4 + 255) / 256, 256>>>(x, xh, xl, n4);
        n4 = QKV_N * D_MODEL / 4;
        split_bf16_kernel<<<(n4 + 255) / 256, 256>>>(w_qkv, wqh, wql, n4);
        n4 = D_MODEL * D_MODEL / 4;
        split_bf16_kernel<<<(n4 + 255) / 256, 256>>>(w_proj, wph, wpl, n4);
    }

    // 1) QKV = X * Wqkv^T   [8192 x 3072]
    {
        dim3 grid(QKV_N / GBN, MROWS / GBM);
        gemm_bf16x3_kernel<<<grid, 256, GEMM_DSM>>>(xh, xl, wqh, wql, qkv, QKV_N, D_MODEL);
    }
    // 2) causal attention -> y [8192 x 1024] (fp32)
    {
        dim3 grid(SEQ / 64, BATCH * NHEAD);
        attn_kernel<<<grid, 256, 65536>>>(qkv, yb);
    }
    // split y, then 3) out = y * Wproj^T  [8192 x 1024]
    {
        int n4 = MROWS * D_MODEL / 4;
        split_bf16_kernel<<<(n4 + 255) / 256, 256>>>(yb, yh, yl, n4);
        dim3 grid(D_MODEL / GBN, MROWS / GBM);
        gemm_bf16x3_kernel<<<grid, 256, GEMM_DSM>>>(yh, yl, wph, wpl, out, D_MODEL, D_MODEL);
    }
}

// round 5
// speedup vs baseline: 4.0623x; 1.9958x over previous
#include <cuda_runtime.h>
#include <cuda_bf16.h>
#include <cstdint>

#define D_MODEL 1024
#define NHEAD   16
#define HDIM    64
#define BATCH   4
#define SEQ     2048
#define MROWS   (BATCH * SEQ)      /* 8192 */
#define QKV_N   (3 * D_MODEL)      /* 3072 */

// Arch-specific feature gate: tcgen05/TMEM only exist on sm_10xa / sm_10xf
#if defined(__CUDA_ARCH_FEAT_SM103_ALL) || defined(__CUDA_ARCH_FEAT_SM100_ALL) || \
    defined(__CUDA_ARCH_FEAT_SM101_ALL) || \
    (defined(__CUDA_ARCH_SPECIFIC__) && (__CUDA_ARCH_SPECIFIC__ >= 1000)) || \
    (defined(__CUDA_ARCH_FAMILY_SPECIFIC__) && (__CUDA_ARCH_FAMILY_SPECIFIC__ >= 1000))
#define TC5 1
#else
#define TC5 0
#endif

// ---------------- scratch (no allocs allowed) ----------------
__device__ float g_qkv[(size_t)MROWS * QKV_N];   // fp32 qkv activations
__device__ float g_y[(size_t)MROWS * D_MODEL];   // fp32 attention output

__device__ __nv_bfloat16 g_xh[(size_t)MROWS * D_MODEL];
__device__ __nv_bfloat16 g_xl[(size_t)MROWS * D_MODEL];
__device__ __nv_bfloat16 g_wqh[(size_t)QKV_N * D_MODEL];
__device__ __nv_bfloat16 g_wql[(size_t)QKV_N * D_MODEL];
__device__ __nv_bfloat16 g_yh[(size_t)MROWS * D_MODEL];
__device__ __nv_bfloat16 g_yl[(size_t)MROWS * D_MODEL];
__device__ __nv_bfloat16 g_wph[(size_t)D_MODEL * D_MODEL];
__device__ __nv_bfloat16 g_wpl[(size_t)D_MODEL * D_MODEL];

// ---------------- generic helpers (legal on all targets) ----------------
__device__ __forceinline__ uint32_t smem_u32(const void* p) {
    uint32_t a;
    asm("{ .reg .u64 t; cvta.to.shared.u64 t, %1; cvt.u32.u64 %0, t; }" : "=r"(a) : "l"(p));
    return a;
}
__device__ __forceinline__ void cp16(uint32_t dst, const void* src) {
    asm volatile("cp.async.cg.shared.global [%0], [%1], 16;" :: "r"(dst), "l"(src) : "memory");
}
__device__ __forceinline__ void cp_commit() { asm volatile("cp.async.commit_group;" ::: "memory"); }
__device__ __forceinline__ void cp_wait1()  { asm volatile("cp.async.wait_group 1;" ::: "memory"); }
__device__ __forceinline__ void cp_wait0()  { asm volatile("cp.async.wait_group 0;" ::: "memory"); }
__device__ __forceinline__ uint32_t swz(uint32_t x) { return x ^ ((x >> 3) & 0x70); }
__device__ __forceinline__ void sts128(uint32_t addr, uint32_t a, uint32_t b, uint32_t c, uint32_t d) {
    asm volatile("st.shared.v4.b32 [%0], {%1,%2,%3,%4};" :: "r"(addr), "r"(a), "r"(b), "r"(c), "r"(d) : "memory");
}
__device__ __forceinline__ void sts16(uint32_t addr, unsigned short v) {
    asm volatile("st.shared.b16 [%0], %1;" :: "r"(addr), "h"(v) : "memory");
}

// ---------------- tcgen05 helpers (sm_103a pass only) ----------------
#if TC5
__device__ __forceinline__ uint32_t elect_one() {
    uint32_t p;
    asm volatile("{\n\t.reg .pred p;\n\telect.sync _|p, 0xFFFFFFFF;\n\tselp.b32 %0, 1, 0, p;\n\t}" : "=r"(p));
    return p;
}
__device__ __forceinline__ void mbar_init(uint32_t mbar, uint32_t cnt) {
    asm volatile("mbarrier.init.shared.b64 [%0], %1;" :: "r"(mbar), "r"(cnt) : "memory");
}
__device__ __forceinline__ void mbar_wait(uint32_t mbar, uint32_t parity) {
    asm volatile(
        "{\n\t.reg .pred P;\n\t"
        "W%=:\n\t"
        "mbarrier.try_wait.parity.shared.b64 P, [%0], %1;\n\t"
        "@!P bra W%=;\n\t}"
        :: "r"(mbar), "r"(parity) : "memory");
}
__device__ __forceinline__ void tmem_alloc(uint32_t smem_dst, uint32_t ncols) {
    asm volatile("tcgen05.alloc.cta_group::1.sync.aligned.shared::cta.b32 [%0], %1;"
                 :: "r"(smem_dst), "r"(ncols) : "memory");
}
__device__ __forceinline__ void tmem_dealloc(uint32_t tmem, uint32_t ncols) {
    asm volatile("tcgen05.dealloc.cta_group::1.sync.aligned.b32 %0, %1;" :: "r"(tmem), "r"(ncols));
}
__device__ __forceinline__ void tmem_relinquish() {
    asm volatile("tcgen05.relinquish_alloc_permit.cta_group::1.sync.aligned;");
}
__device__ __forceinline__ void tc_commit(uint32_t mbar) {
    asm volatile("tcgen05.commit.cta_group::1.mbarrier::arrive::one.shared::cluster.b64 [%0];"
                 :: "r"(mbar) : "memory");
}
__device__ __forceinline__ void tc_fence_after() {
    asm volatile("tcgen05.fence::after_thread_sync;" ::: "memory");
}
__device__ __forceinline__ void tc_fence_before() {
    asm volatile("tcgen05.fence::before_thread_sync;" ::: "memory");
}
__device__ __forceinline__ void fence_async_proxy() {
    asm volatile("fence.proxy.async.shared::cta;" ::: "memory");
}
__device__ __forceinline__ void mma_bf16_ss(uint32_t d, uint64_t a, uint64_t b,
                                            uint32_t idesc, uint32_t acc) {
    asm volatile(
        "{\n\t.reg .pred p;\n\t"
        "setp.ne.u32 p, %5, 0;\n\t"
        "tcgen05.mma.cta_group::1.kind::f16 [%0], %1, %2, %3, {%4, %4, %4, %4}, p;\n\t}"
        :: "r"(d), "l"(a), "l"(b), "r"(idesc), "r"(0u), "r"(acc) : "memory");
}
__device__ __forceinline__ uint64_t mkdesc(uint32_t addr) {
    // SW128, Blackwell version=1, SBO=64, LBO=1 (K-major, 128B rows / contiguous 1KB atoms)
    constexpr uint64_t base = (uint64_t(2) << 61) | (uint64_t(1) << 46)
                            | (uint64_t(64) << 32) | (uint64_t(1) << 16);
    return base | ((addr >> 4) & 0x3FFF);
}
#define LDTM_X32(r, tmem_addr) \
    asm volatile( \
        "tcgen05.ld.sync.aligned.32x32b.x32.b32 " \
        "{%0, %1, %2, %3, %4, %5, %6, %7, " \
        " %8, %9, %10, %11, %12, %13, %14, %15, " \
        " %16, %17, %18, %19, %20, %21, %22, %23, " \
        " %24, %25, %26, %27, %28, %29, %30, %31}, [%32];" \
        : "=r"((r)[0]),  "=r"((r)[1]),  "=r"((r)[2]),  "=r"((r)[3]), \
          "=r"((r)[4]),  "=r"((r)[5]),  "=r"((r)[6]),  "=r"((r)[7]), \
          "=r"((r)[8]),  "=r"((r)[9]),  "=r"((r)[10]), "=r"((r)[11]), \
          "=r"((r)[12]), "=r"((r)[13]), "=r"((r)[14]), "=r"((r)[15]), \
          "=r"((r)[16]), "=r"((r)[17]), "=r"((r)[18]), "=r"((r)[19]), \
          "=r"((r)[20]), "=r"((r)[21]), "=r"((r)[22]), "=r"((r)[23]), \
          "=r"((r)[24]), "=r"((r)[25]), "=r"((r)[26]), "=r"((r)[27]), \
          "=r"((r)[28]), "=r"((r)[29]), "=r"((r)[30]), "=r"((r)[31]) \
        : "r"(tmem_addr))
#define TC_WAIT_LD() asm volatile("tcgen05.wait::ld.sync.aligned;" ::: "memory")
#endif  // TC5

// ---------------- fp32 -> bf16 hi/lo split ----------------
__global__ void __launch_bounds__(256) split_bf16_kernel(
    const float* __restrict__ in, __nv_bfloat16* __restrict__ hi,
    __nv_bfloat16* __restrict__ lo, int n4)
{
    int i = blockIdx.x * blockDim.x + threadIdx.x;
    if (i >= n4) return;
    float4 v = ((const float4*)in)[i];
    __nv_bfloat16 h0 = __float2bfloat16_rn(v.x);
    __nv_bfloat16 h1 = __float2bfloat16_rn(v.y);
    __nv_bfloat16 h2 = __float2bfloat16_rn(v.z);
    __nv_bfloat16 h3 = __float2bfloat16_rn(v.w);
    __nv_bfloat16 l0 = __float2bfloat16_rn(v.x - __bfloat162float(h0));
    __nv_bfloat16 l1 = __float2bfloat16_rn(v.y - __bfloat162float(h1));
    __nv_bfloat16 l2 = __float2bfloat16_rn(v.z - __bfloat162float(h2));
    __nv_bfloat16 l3 = __float2bfloat16_rn(v.w - __bfloat162float(h3));
    ((__nv_bfloat162*)hi)[2 * i + 0] = __nv_bfloat162(h0, h1);
    ((__nv_bfloat162*)hi)[2 * i + 1] = __nv_bfloat162(h2, h3);
    ((__nv_bfloat162*)lo)[2 * i + 0] = __nv_bfloat162(l0, l1);
    ((__nv_bfloat162*)lo)[2 * i + 1] = __nv_bfloat162(l2, l3);
}

// ---------------- GEMM: C[M,N] = A[M,K] * B[N,K]^T (unchanged, R3-proven) --
#define GBM 128
#define GBN 256
#define GBK 64
#define AH_OFF 0
#define AL_OFF 16384
#define BH_OFF 32768
#define BL_OFF 65536
#define STAGE_BYTES 98304
#define GEMM_DSM (1024 + 2 * STAGE_BYTES)
#define GEMM_IDESC 0x8400490u   /* f32 dtype, bf16 a/b, M=128, N=256 */

__device__ __forceinline__ void load_stage(
    uint32_t sbase, const __nv_bfloat16* __restrict__ Ah, const __nv_bfloat16* __restrict__ Al,
    const __nv_bfloat16* __restrict__ Bh, const __nv_bfloat16* __restrict__ Bl,
    int m0, int n0, int kc, int K, int tid)
{
    const int k0 = kc * GBK;
    for (int i = tid; i < 1024; i += 256) {
        int row = i >> 3, seg = i & 7;
        uint32_t so = swz((uint32_t)(row * 128 + seg * 16));
        size_t g = (size_t)(m0 + row) * K + k0 + seg * 8;
        cp16(sbase + AH_OFF + so, Ah + g);
        cp16(sbase + AL_OFF + so, Al + g);
    }
    for (int i = tid; i < 2048; i += 256) {
        int row = i >> 3, seg = i & 7;
        uint32_t so = swz((uint32_t)(row * 128 + seg * 16));
        size_t g = (size_t)(n0 + row) * K + k0 + seg * 8;
        cp16(sbase + BH_OFF + so, Bh + g);
        cp16(sbase + BL_OFF + so, Bl + g);
    }
    cp_commit();
}

__global__ void __launch_bounds__(256)
gemm_bf16x3_kernel(const __nv_bfloat16* __restrict__ Ah, const __nv_bfloat16* __restrict__ Al,
                   const __nv_bfloat16* __restrict__ Bh, const __nv_bfloat16* __restrict__ Bl,
                   float* __restrict__ C, int N, int K)
{
    extern __shared__ char dsm[];
    const int tid = threadIdx.x;
    const int m0 = blockIdx.y * GBM;
    const int n0 = blockIdx.x * GBN;
    uint32_t tile = (smem_u32(dsm) + 1023) & ~1023u;
    const int NC = K / GBK;

#if TC5
    __shared__ uint32_t s_tmem;
    __shared__ __align__(8) unsigned long long s_mbar[2];
    const int wid = tid >> 5;
    const int lane = tid & 31;

    if (wid == 0) {
        tmem_alloc(smem_u32(&s_tmem), 256);
        tmem_relinquish();
    }
    if (tid == 0) {
        mbar_init(smem_u32(&s_mbar[0]), 1);
        mbar_init(smem_u32(&s_mbar[1]), 1);
    }
    __syncthreads();
    const uint32_t tmem = s_tmem;
    const uint32_t mb[2] = { smem_u32(&s_mbar[0]), smem_u32(&s_mbar[1]) };

    load_stage(tile + 0 * STAGE_BYTES, Ah, Al, Bh, Bl, m0, n0, 0, K, tid);
    load_stage(tile + 1 * STAGE_BYTES, Ah, Al, Bh, Bl, m0, n0, 1, K, tid);

    uint32_t ph[2] = {0, 0};
    for (int c = 0; c < NC; c++) {
        const int s = c & 1;
        if (c + 1 < NC) cp_wait1(); else cp_wait0();
        fence_async_proxy();
        __syncthreads();

        if (wid == 0 && elect_one()) {
            uint32_t sb = tile + s * STAGE_BYTES;
            uint64_t dah = mkdesc(sb + AH_OFF);
            uint64_t dal = mkdesc(sb + AL_OFF);
            uint64_t dbh = mkdesc(sb + BH_OFF);
            uint64_t dbl = mkdesc(sb + BL_OFF);
#pragma unroll
            for (int kk = 0; kk < 4; kk++) {
                mma_bf16_ss(tmem, dah + kk * 2, dbh + kk * 2, GEMM_IDESC,
                            (c == 0 && kk == 0) ? 0u : 1u);
                mma_bf16_ss(tmem, dah + kk * 2, dbl + kk * 2, GEMM_IDESC, 1u);
                mma_bf16_ss(tmem, dal + kk * 2, dbh + kk * 2, GEMM_IDESC, 1u);
            }
            tc_commit(mb[s]);
        }

        if (c + 2 < NC) {
            mbar_wait(mb[s], ph[s]);
            ph[s] ^= 1;
            load_stage(tile + s * STAGE_BYTES, Ah, Al, Bh, Bl, m0, n0, c + 2, K, tid);
        }
    }
    mbar_wait(mb[0], ph[0]);
    mbar_wait(mb[1], ph[1]);
    tc_fence_after();

    {
        const int colbase = (wid >> 2) * 128;
        const int row = m0 + (wid & 3) * 32 + lane;
#pragma unroll
        for (int cb = 0; cb < 4; cb++) {
            uint32_t r[32];
            LDTM_X32(r, tmem + colbase + cb * 32);
            TC_WAIT_LD();
            float* Cp = C + (size_t)row * N + n0 + colbase + cb * 32;
#pragma unroll
            for (int j = 0; j < 8; j++) {
                *(float4*)(Cp + j * 4) = make_float4(
                    __uint_as_float(r[j * 4 + 0]), __uint_as_float(r[j * 4 + 1]),
                    __uint_as_float(r[j * 4 + 2]), __uint_as_float(r[j * 4 + 3]));
            }
        }
    }
    tc_fence_before();
    __syncthreads();
    if (wid == 0) tmem_dealloc(tmem, 256);
#else
    (void)tile; (void)NC; (void)Ah; (void)Al; (void)Bh; (void)Bl; (void)C;
#endif
}

// ---------------------------------------------------------------------------
// tcgen05 flash attention, bf16 3-term split everywhere, fp32 accumulate.
// Grid (SEQ/128, BATCH*NHEAD), 128 threads. One thread = one query row.
// ---------------------------------------------------------------------------
#define ATTN_DSM (163840 + 1024)
#define IDESC_S 0x8200490u   /* M=128, N=128 */
#define IDESC_O 0x8100490u   /* M=128, N=64  */

__global__ void __launch_bounds__(128)
attn_tc_kernel(const float* __restrict__ qkv, float* __restrict__ y)
{
#if TC5
    extern __shared__ char dsm[];
    __shared__ uint32_t s_tmem;
    __shared__ __align__(8) unsigned long long s_mbar[2];

    const int tid = threadIdx.x;
    const int wid = tid >> 5;
    const int qt = blockIdx.x;
    const int bh = blockIdx.y;
    const int b  = bh >> 4;
    const int h  = bh & 15;
    const int q0 = qt * 128;

    const uint32_t base0 = (smem_u32(dsm) + 1023) & ~1023u;
    const uint32_t sQh = base0;
    const uint32_t sQl = base0 + 16384;
    const uint32_t sKh = base0 + 32768;
    const uint32_t sKl = base0 + 49152;
    const uint32_t sVh = base0 + 65536;   // V^T [64 d][128 k], 8x2 atoms
    const uint32_t sVl = base0 + 81920;
    const uint32_t sPh = base0 + 98304;   // P [128 q][128 k], 16x2 atoms
    const uint32_t sPl = base0 + 131072;

    if (wid == 0) {
        tmem_alloc(smem_u32(&s_tmem), 256);
        tmem_relinquish();
    }
    if (tid == 0) {
        mbar_init(smem_u32(&s_mbar[0]), 1);
        mbar_init(smem_u32(&s_mbar[1]), 1);
    }
    __syncthreads();
    const uint32_t tmS = s_tmem;
    const uint32_t tmO = s_tmem + 128;
    const uint32_t mb0 = smem_u32(&s_mbar[0]);
    const uint32_t mb1 = smem_u32(&s_mbar[1]);

    const size_t rowbase = (size_t)(b * SEQ) * QKV_N;

    // ---- load Q row tid (pre-scaled), split to hi/lo, K-major SW128 ----
    {
        const float* src = qkv + rowbase + (size_t)(q0 + tid) * QKV_N + h * HDIM;
#pragma unroll
        for (int seg = 0; seg < 8; seg++) {
            float4 a = *(const float4*)(src + seg * 8);
            float4 c = *(const float4*)(src + seg * 8 + 4);
            float vv[8] = {a.x, a.y, a.z, a.w, c.x, c.y, c.z, c.w};
            uint32_t hj[4], lj[4];
#pragma unroll
            for (int p = 0; p < 4; p++) {
                float f0 = vv[2 * p] * 0.125f, f1 = vv[2 * p + 1] * 0.125f;
                __nv_bfloat16 h0 = __float2bfloat16_rn(f0), h1 = __float2bfloat16_rn(f1);
                __nv_bfloat16 l0 = __float2bfloat16_rn(f0 - __bfloat162float(h0));
                __nv_bfloat16 l1 = __float2bfloat16_rn(f1 - __bfloat162float(h1));
                __nv_bfloat162 hp = __halves2bfloat162(h0, h1);
                __nv_bfloat162 lp = __halves2bfloat162(l0, l1);
                hj[p] = *(uint32_t*)&hp;
                lj[p] = *(uint32_t*)&lp;
            }
            uint32_t off = swz((uint32_t)(tid * 128 + seg * 16));
            sts128(sQh + off, hj[0], hj[1], hj[2], hj[3]);
            sts128(sQl + off, lj[0], lj[1], lj[2], lj[3]);
        }
    }

    float m = -1e30f, l = 0.f;
    float o[64];
#pragma unroll
    for (int d = 0; d < 64; d++) o[d] = 0.f;
    uint32_t ph0 = 0, ph1 = 0;

    for (int t = 0; t <= qt; t++) {
        const int k0 = t * 128;
        __syncthreads();   // prior-tile MMAs done (mbar-waited); smem reusable

        // ---- load K row tid (hi/lo, K-major) + V row tid (transposed) ----
        {
            const float* ks = qkv + rowbase + (size_t)(k0 + tid) * QKV_N + D_MODEL + h * HDIM;
#pragma unroll
            for (int seg = 0; seg < 8; seg++) {
                float4 a = *(const float4*)(ks + seg * 8);
                float4 c = *(const float4*)(ks + seg * 8 + 4);
                float vv[8] = {a.x, a.y, a.z, a.w, c.x, c.y, c.z, c.w};
                uint32_t hj[4], lj[4];
#pragma unroll
                for (int p = 0; p < 4; p++) {
                    float f0 = vv[2 * p], f1 = vv[2 * p + 1];
                    __nv_bfloat16 h0 = __float2bfloat16_rn(f0), h1 = __float2bfloat16_rn(f1);
                    __nv_bfloat16 l0 = __float2bfloat16_rn(f0 - __bfloat162float(h0));
                    __nv_bfloat16 l1 = __float2bfloat16_rn(f1 - __bfloat162float(h1));
                    __nv_bfloat162 hp = __halves2bfloat162(h0, h1);
                    __nv_bfloat162 lp = __halves2bfloat162(l0, l1);
                    hj[p] = *(uint32_t*)&hp;
                    lj[p] = *(uint32_t*)&lp;
                }
                uint32_t off = swz((uint32_t)(tid * 128 + seg * 16));
                sts128(sKh + off, hj[0], hj[1], hj[2], hj[3]);
                sts128(sKl + off, lj[0], lj[1], lj[2], lj[3]);
            }
            // V: read row k=tid (64 d-values), store transposed at [d][tid]
            const float* vs = qkv + rowbase + (size_t)(k0 + tid) * QKV_N + 2 * D_MODEL + h * HDIM;
            const uint32_t acol = (uint32_t)(tid >> 6) * 8;    // atom_col * 8 atom-rows
            const uint32_t kin = (uint32_t)(tid & 63) * 2;
#pragma unroll
            for (int d = 0; d < 64; d++) {
                float f = vs[d];
                __nv_bfloat16 hb = __float2bfloat16_rn(f);
                __nv_bfloat16 lb = __float2bfloat16_rn(f - __bfloat162float(hb));
                uint32_t off = swz(((uint32_t)(d >> 3) + acol) * 1024 + (uint32_t)(d & 7) * 128 + kin);
                sts16(sVh + off, __bfloat16_as_ushort(hb));
                sts16(sVl + off, __bfloat16_as_ushort(lb));
            }
        }
        fence_async_proxy();
        __syncthreads();

        // ---- S = Q K^T (3-term split, 4 K-steps) ----
        if (wid == 0 && elect_one()) {
            tc_fence_after();   // order prior LDTM reads of S cols before overwrite
            uint64_t dQh = mkdesc(sQh), dQl = mkdesc(sQl);
            uint64_t dKh = mkdesc(sKh), dKl = mkdesc(sKl);
#pragma unroll
            for (int ks = 0; ks < 4; ks++) {
                mma_bf16_ss(tmS, dQh + 2 * ks, dKh + 2 * ks, IDESC_S, ks ? 1u : 0u);
                mma_bf16_ss(tmS, dQh + 2 * ks, dKl + 2 * ks, IDESC_S, 1u);
                mma_bf16_ss(tmS, dQl + 2 * ks, dKh + 2 * ks, IDESC_S, 1u);
            }
            tc_commit(mb0);
        }
        mbar_wait(mb0, ph0); ph0 ^= 1;
        tc_fence_after();

        // ---- read S row (128 cols), mask, online softmax ----
        float sv[128];
        {
            uint32_t rr[32];
#pragma unroll
            for (int cb = 0; cb < 4; cb++) {
                LDTM_X32(rr, tmS + cb * 32);
                TC_WAIT_LD();
#pragma unroll
                for (int j = 0; j < 32; j++) sv[cb * 32 + j] = __uint_as_float(rr[j]);
            }
        }
        tc_fence_before();   // order LDTM of S before next-tile S-MMA overwrite
        if (t == qt) {
#pragma unroll
            for (int j = 0; j < 128; j++)
                if (j > tid) sv[j] = -1e30f;
        }
        float mx = -1e30f;
#pragma unroll
        for (int j = 0; j < 128; j++) mx = fmaxf(mx, sv[j]);
        const float mnew = fmaxf(m, mx);
        const float alpha = __expf(m - mnew);
        float sum = 0.f;
#pragma unroll
        for (int j = 0; j < 128; j++) {
            float p = __expf(sv[j] - mnew);
            sv[j] = p;
            sum += p;
        }
        l = l * alpha + sum;
        m = mnew;
#pragma unroll
        for (int d = 0; d < 64; d++) o[d] *= alpha;

        // ---- store P (hi/lo) into blocked-atom smem (FULL 8 segs/atom-col) ----
        {
            const uint32_t prow = (uint32_t)(tid >> 3) * 1024 + (uint32_t)(tid & 7) * 128;
#pragma unroll
            for (int jc = 0; jc < 2; jc++) {
                const uint32_t rb = prow + (uint32_t)jc * 16384;
#pragma unroll
                for (int seg = 0; seg < 8; seg++) {   // 8 x 16B = 128B = 64 bf16
                    uint32_t hj[4], lj[4];
#pragma unroll
                    for (int p = 0; p < 4; p++) {
                        float f0 = sv[jc * 64 + seg * 8 + 2 * p];
                        float f1 = sv[jc * 64 + seg * 8 + 2 * p + 1];
                        __nv_bfloat16 h0 = __float2bfloat16_rn(f0), h1 = __float2bfloat16_rn(f1);
                        __nv_bfloat16 l0 = __float2bfloat16_rn(f0 - __bfloat162float(h0));
                        __nv_bfloat16 l1 = __float2bfloat16_rn(f1 - __bfloat162float(h1));
                        __nv_bfloat162 hp = __halves2bfloat162(h0, h1);
                        __nv_bfloat162 lp = __halves2bfloat162(l0, l1);
                        hj[p] = *(uint32_t*)&hp;
                        lj[p] = *(uint32_t*)&lp;
                    }
                    uint32_t off = swz(rb + seg * 16);
                    sts128(sPh + off, hj[0], hj[1], hj[2], hj[3]);
                    sts128(sPl + off, lj[0], lj[1], lj[2], lj[3]);
                }
            }
        }
        fence_async_proxy();
        __syncthreads();

        // ---- O_tile = P V (3-term, 8 K-steps), fresh accumulate ----
        if (wid == 0 && elect_one()) {
            tc_fence_after();   // order prior LDTM reads of O cols before overwrite
            uint64_t dPh = mkdesc(sPh), dPl = mkdesc(sPl);
            uint64_t dVh = mkdesc(sVh), dVl = mkdesc(sVl);
#pragma unroll
            for (int ks = 0; ks < 8; ks++) {
                uint64_t op = (ks < 4) ? (uint64_t)(2 * ks) : (uint64_t)(1024 + 2 * (ks - 4));
                uint64_t ov = (ks < 4) ? (uint64_t)(2 * ks) : (uint64_t)(512 + 2 * (ks - 4));
                mma_bf16_ss(tmO, dPh + op, dVh + ov, IDESC_O, ks ? 1u : 0u);
                mma_bf16_ss(tmO, dPh + op, dVl + ov, IDESC_O, 1u);
                mma_bf16_ss(tmO, dPl + op, dVh + ov, IDESC_O, 1u);
            }
            tc_commit(mb1);
        }
        mbar_wait(mb1, ph1); ph1 ^= 1;
        tc_fence_after();
        {
            uint32_t rr[32];
            LDTM_X32(rr, tmO);
            TC_WAIT_LD();
#pragma unroll
            for (int j = 0; j < 32; j++) o[j] += __uint_as_float(rr[j]);
            LDTM_X32(rr, tmO + 32);
            TC_WAIT_LD();
#pragma unroll
            for (int j = 0; j < 32; j++) o[32 + j] += __uint_as_float(rr[j]);
        }
        tc_fence_before();   // order LDTM of O before next-tile O-MMA overwrite
    }

    // ---- write y row [B,T,H*64] ----
    {
        const float inv = 1.f / l;
        float* dst = y + (size_t)(b * SEQ + q0 + tid) * D_MODEL + h * HDIM;
#pragma unroll
        for (int i = 0; i < 16; i++)
            *(float4*)(dst + 4 * i) = make_float4(o[4 * i] * inv, o[4 * i + 1] * inv,
                                                  o[4 * i + 2] * inv, o[4 * i + 3] * inv);
    }
    __syncthreads();
    if (wid == 0) tmem_dealloc(s_tmem, 256);
#else
    (void)qkv; (void)y;
#endif
}

// ---------------------------------------------------------------------------
extern "C" void kernel_launch(void* const* d_in, const int* in_sizes, int n_in,
                              void* d_out, int out_size)
{
    const float* x      = (const float*)d_in[0];
    const float* w_qkv  = (const float*)d_in[1];
    const float* w_proj = (const float*)d_in[2];
    float* out = (float*)d_out;

    float *qkv, *yb;
    __nv_bfloat16 *xh, *xl, *wqh, *wql, *yh, *yl, *wph, *wpl;
    cudaGetSymbolAddress((void**)&qkv, g_qkv);
    cudaGetSymbolAddress((void**)&yb,  g_y);
    cudaGetSymbolAddress((void**)&xh,  g_xh);
    cudaGetSymbolAddress((void**)&xl,  g_xl);
    cudaGetSymbolAddress((void**)&wqh, g_wqh);
    cudaGetSymbolAddress((void**)&wql, g_wql);
    cudaGetSymbolAddress((void**)&yh,  g_yh);
    cudaGetSymbolAddress((void**)&yl,  g_yl);
    cudaGetSymbolAddress((void**)&wph, g_wph);
    cudaGetSymbolAddress((void**)&wpl, g_wpl);

    cudaFuncSetAttribute(gemm_bf16x3_kernel, cudaFuncAttributeMaxDynamicSharedMemorySize, GEMM_DSM);
    cudaFuncSetAttribute(attn_tc_kernel, cudaFuncAttributeMaxDynamicSharedMemorySize, ATTN_DSM);

    // split inputs to bf16 hi/lo
    {
        int n4 = MROWS * D_MODEL / 4;
        split_bf16_kernel<<<(n4 + 255) / 256, 256>>>(x, xh, xl, n4);
        n4 = QKV_N * D_MODEL / 4;
        split_bf16_kernel<<<(n4 + 255) / 256, 256>>>(w_qkv, wqh, wql, n4);
        n4 = D_MODEL * D_MODEL / 4;
        split_bf16_kernel<<<(n4 + 255) / 256, 256>>>(w_proj, wph, wpl, n4);
    }

    // 1) QKV = X * Wqkv^T   [8192 x 3072]
    {
        dim3 grid(QKV_N / GBN, MROWS / GBM);
        gemm_bf16x3_kernel<<<grid, 256, GEMM_DSM>>>(xh, xl, wqh, wql, qkv, QKV_N, D_MODEL);
    }
    // 2) causal attention -> y [8192 x 1024] (tcgen05)
    {
        dim3 grid(SEQ / 128, BATCH * NHEAD);
        attn_tc_kernel<<<grid, 128, ATTN_DSM>>>(qkv, yb);
    }
    // split y, then 3) out = y * Wproj^T  [8192 x 1024]
    {
        int n4 = MROWS * D_MODEL / 4;
        split_bf16_kernel<<<(n4 + 255) / 256, 256>>>(yb, yh, yl, n4);
        dim3 grid(D_MODEL / GBN, MROWS / GBM);
        gemm_bf16x3_kernel<<<grid, 256, GEMM_DSM>>>(yh, yl, wph, wpl, out, D_MODEL, D_MODEL);
    }
}